// round 2
// baseline (speedup 1.0000x reference)
#include <cuda_runtime.h>
#include <cuda_bf16.h>
#include <cstdint>

// Problem constants
constexpr int Bc   = 2;
constexpr int Tc   = 2048;
constexpr int Cc   = 1024;
constexpr int HEAD = 16;
constexpr int DH   = 64;
constexpr int Wqkv = 3 * Cc;     // 3072
constexpr int Mrows = Bc * Tc;   // 4096

// Scratch (allocation-free rule: device globals)
__device__ float g_qkv[(size_t)Mrows * Wqkv]; // [B,T,3C]
__device__ float g_y  [(size_t)Mrows * Cc];   // [B,T,C] (heads concatenated)

// ---------------------------------------------------------------------------
// SGEMM: C[M,N] = A[M,K] @ B[K,N] + bias[N]
// 128x128x16 tile, 256 threads, 8x8 per thread. Dims must divide tiles (they do).
// ---------------------------------------------------------------------------
__global__ __launch_bounds__(256) void sgemm_bias_kernel(
    const float* __restrict__ A, const float* __restrict__ Bm,
    const float* __restrict__ bias, float* __restrict__ Cm,
    int M, int N, int K)
{
    constexpr int BM = 128, BN = 128, BK = 16;
    __shared__ float As[BK][BM + 4];   // transposed A tile, padded
    __shared__ float Bs[BK][BN];

    const int tid = threadIdx.x;
    const int tm  = tid >> 4;          // 0..15
    const int tn  = tid & 15;          // 0..15
    const int bm  = blockIdx.y * BM;
    const int bn  = blockIdx.x * BN;

    const float* Ag = A  + (size_t)bm * K;
    const float* Bg = Bm + bn;

    float acc[8][8];
    #pragma unroll
    for (int i = 0; i < 8; ++i)
        #pragma unroll
        for (int j = 0; j < 8; ++j) acc[i][j] = 0.f;

    for (int k0 = 0; k0 < K; k0 += BK) {
        // A tile: 128 rows x 16 cols -> As[k][m] (transposed)
        #pragma unroll
        for (int l = 0; l < 2; ++l) {
            int i  = tid + l * 256;        // 0..511
            int r  = i >> 2;               // 0..127
            int c4 = (i & 3) * 4;          // 0,4,8,12
            float4 v = *(const float4*)&Ag[(size_t)r * K + k0 + c4];
            As[c4 + 0][r] = v.x; As[c4 + 1][r] = v.y;
            As[c4 + 2][r] = v.z; As[c4 + 3][r] = v.w;
        }
        // B tile: 16 rows x 128 cols -> Bs[k][n]
        #pragma unroll
        for (int l = 0; l < 2; ++l) {
            int i  = tid + l * 256;
            int r  = i >> 5;               // 0..15
            int c4 = (i & 31) * 4;         // 0..124
            *(float4*)&Bs[r][c4] = *(const float4*)&Bg[(size_t)(k0 + r) * N + c4];
        }
        __syncthreads();

        #pragma unroll
        for (int k = 0; k < BK; ++k) {
            float a[8], b[8];
            *(float4*)&a[0] = *(const float4*)&As[k][tm * 8];
            *(float4*)&a[4] = *(const float4*)&As[k][tm * 8 + 4];
            *(float4*)&b[0] = *(const float4*)&Bs[k][tn * 8];
            *(float4*)&b[4] = *(const float4*)&Bs[k][tn * 8 + 4];
            #pragma unroll
            for (int i = 0; i < 8; ++i)
                #pragma unroll
                for (int j = 0; j < 8; ++j)
                    acc[i][j] += a[i] * b[j];
        }
        __syncthreads();
    }

    // Epilogue: add bias, store
    #pragma unroll
    for (int i = 0; i < 8; ++i) {
        size_t row = (size_t)(bm + tm * 8 + i);
        #pragma unroll
        for (int j4 = 0; j4 < 8; j4 += 4) {
            int col = bn + tn * 8 + j4;
            float4 bv = *(const float4*)&bias[col];
            float4 o;
            o.x = acc[i][j4 + 0] + bv.x;
            o.y = acc[i][j4 + 1] + bv.y;
            o.z = acc[i][j4 + 2] + bv.z;
            o.w = acc[i][j4 + 3] + bv.w;
            *(float4*)&Cm[row * N + col] = o;
        }
    }
}

// ---------------------------------------------------------------------------
// Flash attention (causal), fp32.
// Grid: (T/64, HEAD, B). Block: 256 threads. Tiles 64(q) x 64(k), DH=64.
// Thread (tm,tn): tm=tid/16 owns 4 q-rows, tn=tid%16 owns 4 k-cols / d-cols.
// m/l kept in registers, replicated across the 16-lane row group (shfl_xor).
// ---------------------------------------------------------------------------
constexpr int LDP = 68;  // padded row stride (floats)
constexpr int ATTN_SMEM = 4 * 64 * LDP * (int)sizeof(float); // 69632 B

__global__ __launch_bounds__(256) void attn_kernel(
    const float* __restrict__ qkv, float* __restrict__ y)
{
    extern __shared__ float sm[];
    float (*Qs)[LDP] = (float(*)[LDP])(sm);                // [d][qi]
    float (*Ks)[LDP] = (float(*)[LDP])(sm + 1 * 64 * LDP); // [d][ki]
    float (*Vs)[LDP] = (float(*)[LDP])(sm + 2 * 64 * LDP); // [ki][d]
    float (*Ps)[LDP] = (float(*)[LDP])(sm + 3 * 64 * LDP); // [ki][qi]

    const int tid = threadIdx.x;
    const int tm  = tid >> 4;   // q-row group 0..15
    const int tn  = tid & 15;   // k-col / d-col group 0..15
    const int qt  = blockIdx.x;
    const int h   = blockIdx.y;
    const int b   = blockIdx.z;

    // Load Q tile -> Qs[d][qi]
    const float* Qg = qkv + ((size_t)(b * Tc + qt * 64)) * Wqkv + h * DH;
    for (int i = tid; i < 64 * 16; i += 256) {
        int r = i >> 4, c4 = (i & 15) * 4;
        float4 v = *(const float4*)&Qg[(size_t)r * Wqkv + c4];
        Qs[c4 + 0][r] = v.x; Qs[c4 + 1][r] = v.y;
        Qs[c4 + 2][r] = v.z; Qs[c4 + 3][r] = v.w;
    }

    float m[4], l[4], o[4][4];
    #pragma unroll
    for (int i = 0; i < 4; ++i) {
        m[i] = -1e30f; l[i] = 0.f;
        #pragma unroll
        for (int j = 0; j < 4; ++j) o[i][j] = 0.f;
    }

    const float scale = 0.125f; // 1/sqrt(64)

    for (int kt = 0; kt <= qt; ++kt) {
        const float* Kg = qkv + ((size_t)(b * Tc + kt * 64)) * Wqkv + Cc + h * DH;
        const float* Vg = Kg + Cc;

        __syncthreads();  // prev iter's Ks/Vs/Ps fully consumed
        for (int i = tid; i < 64 * 16; i += 256) {
            int r = i >> 4, c4 = (i & 15) * 4;
            float4 kv = *(const float4*)&Kg[(size_t)r * Wqkv + c4];
            Ks[c4 + 0][r] = kv.x; Ks[c4 + 1][r] = kv.y;
            Ks[c4 + 2][r] = kv.z; Ks[c4 + 3][r] = kv.w;
            float4 vv = *(const float4*)&Vg[(size_t)r * Wqkv + c4];
            *(float4*)&Vs[r][c4] = vv;
        }
        __syncthreads();  // tiles ready (also covers Qs on first iter)

        // S = Q K^T (4x4 per thread)
        float s[4][4];
        #pragma unroll
        for (int i = 0; i < 4; ++i)
            #pragma unroll
            for (int j = 0; j < 4; ++j) s[i][j] = 0.f;

        #pragma unroll 8
        for (int d = 0; d < 64; ++d) {
            float qa[4], ka[4];
            *(float4*)qa = *(const float4*)&Qs[d][tm * 4];
            *(float4*)ka = *(const float4*)&Ks[d][tn * 4];
            #pragma unroll
            for (int i = 0; i < 4; ++i)
                #pragma unroll
                for (int j = 0; j < 4; ++j)
                    s[i][j] += qa[i] * ka[j];
        }

        // scale + causal mask (diag tile only)
        if (kt == qt) {
            #pragma unroll
            for (int i = 0; i < 4; ++i)
                #pragma unroll
                for (int j = 0; j < 4; ++j) {
                    int qr = tm * 4 + i, kc = tn * 4 + j;
                    s[i][j] = (kc <= qr) ? s[i][j] * scale : -1e30f;
                }
        } else {
            #pragma unroll
            for (int i = 0; i < 4; ++i)
                #pragma unroll
                for (int j = 0; j < 4; ++j) s[i][j] *= scale;
        }

        // Online softmax: row stats over the 16-lane group
        float p[4][4];
        #pragma unroll
        for (int i = 0; i < 4; ++i) {
            float mx = fmaxf(fmaxf(s[i][0], s[i][1]), fmaxf(s[i][2], s[i][3]));
            #pragma unroll
            for (int off = 8; off >= 1; off >>= 1)
                mx = fmaxf(mx, __shfl_xor_sync(0xffffffffu, mx, off));
            float mnew  = fmaxf(m[i], mx);
            float alpha = __expf(m[i] - mnew);
            float rs = 0.f;
            #pragma unroll
            for (int j = 0; j < 4; ++j) {
                p[i][j] = __expf(s[i][j] - mnew);
                rs += p[i][j];
            }
            #pragma unroll
            for (int off = 8; off >= 1; off >>= 1)
                rs += __shfl_xor_sync(0xffffffffu, rs, off);
            l[i] = l[i] * alpha + rs;
            m[i] = mnew;
            #pragma unroll
            for (int j = 0; j < 4; ++j) o[i][j] *= alpha;
        }

        // Stage P transposed: Ps[ki][qi]
        #pragma unroll
        for (int i = 0; i < 4; ++i)
            #pragma unroll
            for (int j = 0; j < 4; ++j)
                Ps[tn * 4 + j][tm * 4 + i] = p[i][j];
        __syncthreads();  // Ps ready

        // O += P @ V
        #pragma unroll 8
        for (int ki = 0; ki < 64; ++ki) {
            float pa[4], va[4];
            *(float4*)pa = *(const float4*)&Ps[ki][tm * 4];
            *(float4*)va = *(const float4*)&Vs[ki][tn * 4];
            #pragma unroll
            for (int i = 0; i < 4; ++i)
                #pragma unroll
                for (int j = 0; j < 4; ++j)
                    o[i][j] += pa[i] * va[j];
        }
    }

    // Epilogue: y[b, t, h*64 + d] = O / l
    float* Yg = y + ((size_t)(b * Tc + qt * 64)) * Cc + h * DH;
    #pragma unroll
    for (int i = 0; i < 4; ++i) {
        float inv = 1.f / l[i];
        float4 ov;
        ov.x = o[i][0] * inv; ov.y = o[i][1] * inv;
        ov.z = o[i][2] * inv; ov.w = o[i][3] * inv;
        *(float4*)&Yg[(size_t)(tm * 4 + i) * Cc + tn * 4] = ov;
    }
}

// ---------------------------------------------------------------------------
// Launch
// ---------------------------------------------------------------------------
extern "C" void kernel_launch(void* const* d_in, const int* in_sizes, int n_in,
                              void* d_out, int out_size)
{
    const float* x      = (const float*)d_in[0];
    const float* W_attn = (const float*)d_in[1];
    const float* b_attn = (const float*)d_in[2];
    const float* W_proj = (const float*)d_in[3];
    const float* b_proj = (const float*)d_in[4];
    float* out = (float*)d_out;

    float* qkv_ptr = nullptr;
    float* y_ptr   = nullptr;
    cudaGetSymbolAddress((void**)&qkv_ptr, g_qkv);
    cudaGetSymbolAddress((void**)&y_ptr,   g_y);

    cudaFuncSetAttribute(attn_kernel,
                         cudaFuncAttributeMaxDynamicSharedMemorySize, ATTN_SMEM);

    // 1) QKV = x @ W_attn + b_attn       [4096, 3072]
    {
        dim3 grid(Wqkv / 128, Mrows / 128);
        sgemm_bias_kernel<<<grid, 256>>>(x, W_attn, b_attn, qkv_ptr,
                                         Mrows, Wqkv, Cc);
    }
    // 2) causal flash attention -> g_y   [4096, 1024]
    {
        dim3 grid(Tc / 64, HEAD, Bc);
        attn_kernel<<<grid, 256, ATTN_SMEM>>>(qkv_ptr, y_ptr);
    }
    // 3) out = y @ W_proj + b_proj       [4096, 1024]
    {
        dim3 grid(Cc / 128, Mrows / 128);
        sgemm_bias_kernel<<<grid, 256>>>(y_ptr, W_proj, b_proj, out,
                                         Mrows, Cc, Cc);
    }
}

// round 4
// speedup vs baseline: 2.9428x; 2.9428x over previous
#include <cuda_runtime.h>
#include <cuda_bf16.h>
#include <cstdint>

// Problem constants
constexpr int Bc    = 2;
constexpr int Tc    = 2048;
constexpr int Cc    = 1024;
constexpr int HEAD  = 16;
constexpr int DH    = 64;
constexpr int Wqkv  = 3 * Cc;     // 3072
constexpr int Mrows = Bc * Tc;    // 4096

// Scratch (allocation-free rule: device globals)
__device__ float g_qkv[(size_t)Mrows * Wqkv]; // [B,T,3C]
__device__ float g_y  [(size_t)Mrows * Cc];   // [B,T,C]

// ---------------------------------------------------------------------------
// Helpers
// ---------------------------------------------------------------------------
__device__ __forceinline__ uint32_t f2tf32(float x) {
    uint32_t r;
    asm("cvt.rna.tf32.f32 %0, %1;" : "=r"(r) : "f"(x));
    return r;
}

// D = A(16x8) * B(8x8) + D, tf32 inputs, fp32 accum.
// A row-major frag, B col-major frag (standard m16n8k8 layout).
__device__ __forceinline__ void mma_tf32(float* c, const uint32_t* a, const uint32_t* b) {
    asm volatile(
        "mma.sync.aligned.m16n8k8.row.col.f32.tf32.tf32.f32 "
        "{%0,%1,%2,%3}, {%4,%5,%6,%7}, {%8,%9}, {%0,%1,%2,%3};"
        : "+f"(c[0]), "+f"(c[1]), "+f"(c[2]), "+f"(c[3])
        : "r"(a[0]), "r"(a[1]), "r"(a[2]), "r"(a[3]),
          "r"(b[0]), "r"(b[1]));
}

// ---------------------------------------------------------------------------
// tf32 tensor-core GEMM: C[M,N] = A[M,K] @ B[K,N] + bias[N]
// 128x128x32 tile, 256 threads (8 warps, 2x4), warp tile 64x32.
// ---------------------------------------------------------------------------
__global__ __launch_bounds__(256) void gemm_tf32_kernel(
    const float* __restrict__ A, const float* __restrict__ Bm,
    const float* __restrict__ bias, float* __restrict__ Cm,
    int M, int N, int K)
{
    constexpr int BM = 128, BN = 128, BK = 32;
    constexpr int LDA = 36;   // padded stride (words) for As [BM][LDA]
    constexpr int LDB = 132;  // padded stride for Bs [BK][LDB]
    __shared__ uint32_t As[BM * LDA];
    __shared__ uint32_t Bs[BK * LDB];

    const int tid  = threadIdx.x;
    const int w    = tid >> 5;
    const int lane = tid & 31;
    const int g    = lane >> 2;   // group id 0..7
    const int t    = lane & 3;    // thread-in-group 0..3
    const int wm   = w >> 2;      // 0..1 -> m offset wm*64
    const int wn   = w & 3;       // 0..3 -> n offset wn*32

    const int bm = blockIdx.y * BM;
    const int bn = blockIdx.x * BN;

    float acc[4][4][4];  // [mi][ni][c]
    #pragma unroll
    for (int mi = 0; mi < 4; ++mi)
        #pragma unroll
        for (int ni = 0; ni < 4; ++ni)
            #pragma unroll
            for (int c = 0; c < 4; ++c) acc[mi][ni][c] = 0.f;

    for (int k0 = 0; k0 < K; k0 += BK) {
        // A tile 128x32 (fp32 -> tf32)
        #pragma unroll
        for (int l = 0; l < 4; ++l) {
            int idx = tid + l * 256;       // 0..1023 float4 slots
            int r   = idx >> 3;            // 0..127
            int c4  = (idx & 7) * 4;       // 0..28
            float4 v = *(const float4*)&A[(size_t)(bm + r) * K + k0 + c4];
            uint4 u = make_uint4(f2tf32(v.x), f2tf32(v.y), f2tf32(v.z), f2tf32(v.w));
            *(uint4*)&As[r * LDA + c4] = u;
        }
        // B tile 32x128
        #pragma unroll
        for (int l = 0; l < 4; ++l) {
            int idx = tid + l * 256;
            int r   = idx >> 5;            // 0..31
            int c4  = (idx & 31) * 4;      // 0..124
            float4 v = *(const float4*)&Bm[(size_t)(k0 + r) * N + bn + c4];
            uint4 u = make_uint4(f2tf32(v.x), f2tf32(v.y), f2tf32(v.z), f2tf32(v.w));
            *(uint4*)&Bs[r * LDB + c4] = u;
        }
        __syncthreads();

        #pragma unroll
        for (int kc = 0; kc < 4; ++kc) {
            uint32_t af[4][4], bf[4][2];
            #pragma unroll
            for (int mi = 0; mi < 4; ++mi) {
                int rb = wm * 64 + mi * 16;
                af[mi][0] = As[(rb + g    ) * LDA + kc * 8 + t    ];
                af[mi][1] = As[(rb + g + 8) * LDA + kc * 8 + t    ];
                af[mi][2] = As[(rb + g    ) * LDA + kc * 8 + t + 4];
                af[mi][3] = As[(rb + g + 8) * LDA + kc * 8 + t + 4];
            }
            #pragma unroll
            for (int ni = 0; ni < 4; ++ni) {
                int nb = wn * 32 + ni * 8;
                bf[ni][0] = Bs[(kc * 8 + t    ) * LDB + nb + g];
                bf[ni][1] = Bs[(kc * 8 + t + 4) * LDB + nb + g];
            }
            #pragma unroll
            for (int mi = 0; mi < 4; ++mi)
                #pragma unroll
                for (int ni = 0; ni < 4; ++ni)
                    mma_tf32(acc[mi][ni], af[mi], bf[ni]);
        }
        __syncthreads();
    }

    // Epilogue: add bias, store (float2 per c-pair)
    #pragma unroll
    for (int mi = 0; mi < 4; ++mi) {
        int r0 = bm + wm * 64 + mi * 16 + g;
        #pragma unroll
        for (int ni = 0; ni < 4; ++ni) {
            int col = bn + wn * 32 + ni * 8 + 2 * t;
            float b0 = bias[col], b1 = bias[col + 1];
            float2 v0 = make_float2(acc[mi][ni][0] + b0, acc[mi][ni][1] + b1);
            float2 v1 = make_float2(acc[mi][ni][2] + b0, acc[mi][ni][3] + b1);
            *(float2*)&Cm[(size_t)r0 * N + col]       = v0;
            *(float2*)&Cm[(size_t)(r0 + 8) * N + col] = v1;
        }
    }
}

// ---------------------------------------------------------------------------
// Flash attention (causal) on tf32 tensor cores.
// Grid (T/64, H, B), block 128 (4 warps). Warp owns m16 q-rows.
// K-tile 64, D=64. Online softmax per row in quad groups.
// ---------------------------------------------------------------------------
constexpr int LDK = 68;  // Ks/Qs/Ps stride (words)
constexpr int LDV = 72;  // Vs stride (words)
constexpr int ATTN_SMEM = (64 * LDK + 64 * LDV + 64 * LDK) * (int)sizeof(uint32_t);

__global__ __launch_bounds__(128) void attn_tc_kernel(
    const float* __restrict__ qkv, float* __restrict__ y)
{
    extern __shared__ uint32_t sm[];
    uint32_t* Ks = sm;                         // [64][LDK]  (tok, d) tf32
    uint32_t* Vs = sm + 64 * LDK;              // [64][LDV]  (tok, d) tf32
    uint32_t* Ps = sm + 64 * LDK + 64 * LDV;   // Q staging then P [64][LDK]

    const int tid  = threadIdx.x;
    const int w    = tid >> 5;
    const int lane = tid & 31;
    const int g    = lane >> 2;
    const int t    = lane & 3;
    const int rb   = w * 16;        // warp's q-row base within tile

    const int qt = blockIdx.x;
    const int h  = blockIdx.y;
    const int b  = blockIdx.z;

    // Stage Q (scaled by 1/sqrt(D)) as tf32 into Ps region
    const float scale = 0.125f;
    const float* Qg = qkv + ((size_t)(b * Tc + qt * 64)) * Wqkv + h * DH;
    for (int idx = tid; idx < 64 * 16; idx += 128) {
        int r = idx >> 4, c4 = (idx & 15) * 4;
        float4 v = *(const float4*)&Qg[(size_t)r * Wqkv + c4];
        uint4 u = make_uint4(f2tf32(v.x * scale), f2tf32(v.y * scale),
                             f2tf32(v.z * scale), f2tf32(v.w * scale));
        *(uint4*)&Ps[r * LDK + c4] = u;
    }
    __syncthreads();

    // Q fragments in registers: 8 k-chunks x a[4]
    uint32_t qa[8][4];
    #pragma unroll
    for (int kc = 0; kc < 8; ++kc) {
        qa[kc][0] = Ps[(rb + g    ) * LDK + kc * 8 + t    ];
        qa[kc][1] = Ps[(rb + g + 8) * LDK + kc * 8 + t    ];
        qa[kc][2] = Ps[(rb + g    ) * LDK + kc * 8 + t + 4];
        qa[kc][3] = Ps[(rb + g + 8) * LDK + kc * 8 + t + 4];
    }

    float o[8][4];
    #pragma unroll
    for (int nf = 0; nf < 8; ++nf)
        #pragma unroll
        for (int c = 0; c < 4; ++c) o[nf][c] = 0.f;
    float m0 = -1e30f, m1 = -1e30f, l0 = 0.f, l1 = 0.f;

    for (int kt = 0; kt <= qt; ++kt) {
        __syncthreads();  // previous Ks/Vs (and Q staging) fully consumed
        const float* Kg = qkv + ((size_t)(b * Tc + kt * 64)) * Wqkv + Cc + h * DH;
        const float* Vg = Kg + Cc;
        for (int idx = tid; idx < 64 * 16; idx += 128) {
            int r = idx >> 4, c4 = (idx & 15) * 4;
            float4 kv = *(const float4*)&Kg[(size_t)r * Wqkv + c4];
            *(uint4*)&Ks[r * LDK + c4] =
                make_uint4(f2tf32(kv.x), f2tf32(kv.y), f2tf32(kv.z), f2tf32(kv.w));
            float4 vv = *(const float4*)&Vg[(size_t)r * Wqkv + c4];
            *(uint4*)&Vs[r * LDV + c4] =
                make_uint4(f2tf32(vv.x), f2tf32(vv.y), f2tf32(vv.z), f2tf32(vv.w));
        }
        __syncthreads();

        // S = Q K^T  (8 n-frags of 8 k-tokens)
        float s[8][4];
        #pragma unroll
        for (int ni = 0; ni < 8; ++ni)
            #pragma unroll
            for (int c = 0; c < 4; ++c) s[ni][c] = 0.f;

        #pragma unroll
        for (int kc = 0; kc < 8; ++kc) {
            #pragma unroll
            for (int ni = 0; ni < 8; ++ni) {
                uint32_t bf[2];
                bf[0] = Ks[(ni * 8 + g) * LDK + kc * 8 + t    ];
                bf[1] = Ks[(ni * 8 + g) * LDK + kc * 8 + t + 4];
                mma_tf32(s[ni], qa[kc], bf);
            }
        }

        // Causal mask on diagonal tile
        if (kt == qt) {
            int qr0 = rb + g, qr1 = rb + g + 8;
            #pragma unroll
            for (int ni = 0; ni < 8; ++ni) {
                int c0 = ni * 8 + 2 * t, c1 = c0 + 1;
                if (c0 > qr0) s[ni][0] = -1e30f;
                if (c1 > qr0) s[ni][1] = -1e30f;
                if (c0 > qr1) s[ni][2] = -1e30f;
                if (c1 > qr1) s[ni][3] = -1e30f;
            }
        }

        // Online softmax (rows g and g+8; stats replicated over quad)
        float mx0 = -1e30f, mx1 = -1e30f;
        #pragma unroll
        for (int ni = 0; ni < 8; ++ni) {
            mx0 = fmaxf(mx0, fmaxf(s[ni][0], s[ni][1]));
            mx1 = fmaxf(mx1, fmaxf(s[ni][2], s[ni][3]));
        }
        mx0 = fmaxf(mx0, __shfl_xor_sync(0xffffffffu, mx0, 1));
        mx0 = fmaxf(mx0, __shfl_xor_sync(0xffffffffu, mx0, 2));
        mx1 = fmaxf(mx1, __shfl_xor_sync(0xffffffffu, mx1, 1));
        mx1 = fmaxf(mx1, __shfl_xor_sync(0xffffffffu, mx1, 2));

        float mn0 = fmaxf(m0, mx0), mn1 = fmaxf(m1, mx1);
        float a0 = __expf(m0 - mn0), a1 = __expf(m1 - mn1);

        float rs0 = 0.f, rs1 = 0.f;
        #pragma unroll
        for (int ni = 0; ni < 8; ++ni) {
            s[ni][0] = __expf(s[ni][0] - mn0);
            s[ni][1] = __expf(s[ni][1] - mn0);
            s[ni][2] = __expf(s[ni][2] - mn1);
            s[ni][3] = __expf(s[ni][3] - mn1);
            rs0 += s[ni][0] + s[ni][1];
            rs1 += s[ni][2] + s[ni][3];
        }
        rs0 += __shfl_xor_sync(0xffffffffu, rs0, 1);
        rs0 += __shfl_xor_sync(0xffffffffu, rs0, 2);
        rs1 += __shfl_xor_sync(0xffffffffu, rs1, 1);
        rs1 += __shfl_xor_sync(0xffffffffu, rs1, 2);

        l0 = l0 * a0 + rs0;  m0 = mn0;
        l1 = l1 * a1 + rs1;  m1 = mn1;

        #pragma unroll
        for (int nf = 0; nf < 8; ++nf) {
            o[nf][0] *= a0; o[nf][1] *= a0;
            o[nf][2] *= a1; o[nf][3] *= a1;
        }

        // Stage P (warp-private rows of Ps) as tf32
        #pragma unroll
        for (int ni = 0; ni < 8; ++ni) {
            int c0 = ni * 8 + 2 * t;
            Ps[(rb + g    ) * LDK + c0    ] = f2tf32(s[ni][0]);
            Ps[(rb + g    ) * LDK + c0 + 1] = f2tf32(s[ni][1]);
            Ps[(rb + g + 8) * LDK + c0    ] = f2tf32(s[ni][2]);
            Ps[(rb + g + 8) * LDK + c0 + 1] = f2tf32(s[ni][3]);
        }
        __syncwarp();

        // O += P @ V
        #pragma unroll
        for (int kc = 0; kc < 8; ++kc) {
            uint32_t pa[4];
            pa[0] = Ps[(rb + g    ) * LDK + kc * 8 + t    ];
            pa[1] = Ps[(rb + g + 8) * LDK + kc * 8 + t    ];
            pa[2] = Ps[(rb + g    ) * LDK + kc * 8 + t + 4];
            pa[3] = Ps[(rb + g + 8) * LDK + kc * 8 + t + 4];
            #pragma unroll
            for (int nf = 0; nf < 8; ++nf) {
                uint32_t bf[2];
                bf[0] = Vs[(kc * 8 + t    ) * LDV + nf * 8 + g];
                bf[1] = Vs[(kc * 8 + t + 4) * LDV + nf * 8 + g];
                mma_tf32(o[nf], pa, bf);
            }
        }
        __syncwarp();
    }

    // Epilogue: normalize and store
    float inv0 = 1.f / l0, inv1 = 1.f / l1;
    float* Yg = y + ((size_t)(b * Tc + qt * 64)) * Cc + h * DH;
    #pragma unroll
    for (int nf = 0; nf < 8; ++nf) {
        int c0 = nf * 8 + 2 * t;
        *(float2*)&Yg[(size_t)(rb + g    ) * Cc + c0] =
            make_float2(o[nf][0] * inv0, o[nf][1] * inv0);
        *(float2*)&Yg[(size_t)(rb + g + 8) * Cc + c0] =
            make_float2(o[nf][2] * inv1, o[nf][3] * inv1);
    }
}

// ---------------------------------------------------------------------------
// Launch
// ---------------------------------------------------------------------------
extern "C" void kernel_launch(void* const* d_in, const int* in_sizes, int n_in,
                              void* d_out, int out_size)
{
    const float* x      = (const float*)d_in[0];
    const float* W_attn = (const float*)d_in[1];
    const float* b_attn = (const float*)d_in[2];
    const float* W_proj = (const float*)d_in[3];
    const float* b_proj = (const float*)d_in[4];
    float* out = (float*)d_out;

    float* qkv_ptr = nullptr;
    float* y_ptr   = nullptr;
    cudaGetSymbolAddress((void**)&qkv_ptr, g_qkv);
    cudaGetSymbolAddress((void**)&y_ptr,   g_y);

    cudaFuncSetAttribute(attn_tc_kernel,
                         cudaFuncAttributeMaxDynamicSharedMemorySize, ATTN_SMEM);

    // 1) QKV = x @ W_attn + b_attn   [4096, 3072]
    {
        dim3 grid(Wqkv / 128, Mrows / 128);
        gemm_tf32_kernel<<<grid, 256>>>(x, W_attn, b_attn, qkv_ptr,
                                        Mrows, Wqkv, Cc);
    }
    // 2) causal flash attention -> g_y
    {
        dim3 grid(Tc / 64, HEAD, Bc);
        attn_tc_kernel<<<grid, 128, ATTN_SMEM>>>(qkv_ptr, y_ptr);
    }
    // 3) out = y @ W_proj + b_proj   [4096, 1024]
    {
        dim3 grid(Cc / 128, Mrows / 128);
        gemm_tf32_kernel<<<grid, 256>>>(y_ptr, W_proj, b_proj, out,
                                        Mrows, Cc, Cc);
    }
}

// round 6
// speedup vs baseline: 3.2735x; 1.1124x over previous
#include <cuda_runtime.h>
#include <cuda_bf16.h>
#include <cstdint>

// Problem constants
constexpr int Bc    = 2;
constexpr int Tc    = 2048;
constexpr int Cc    = 1024;
constexpr int HEAD  = 16;
constexpr int DH    = 64;
constexpr int Wqkv  = 3 * Cc;     // 3072
constexpr int Mrows = Bc * Tc;    // 4096

// Scratch (allocation-free rule: device globals)
__device__ float g_qkv[(size_t)Mrows * Wqkv]; // [B,T,3C], tf32-rounded
__device__ float g_y  [(size_t)Mrows * Cc];   // [B,T,C],  tf32-rounded
__device__ float g_xr [(size_t)Mrows * Cc];   // x tf32-rounded
__device__ float g_w1r[(size_t)Cc * Wqkv];    // W_attn tf32-rounded [K][N]
__device__ float g_w2r[(size_t)Cc * Cc];      // W_proj tf32-rounded [K][N]

// ---------------------------------------------------------------------------
// Helpers
// ---------------------------------------------------------------------------
__device__ __forceinline__ uint32_t f2tf32(float x) {
    uint32_t r;
    asm("cvt.rna.tf32.f32 %0, %1;" : "=r"(r) : "f"(x));
    return r;
}

__device__ __forceinline__ uint32_t smem_to_u32(const void* p) {
    uint32_t a;
    asm("{ .reg .u64 t; cvta.to.shared.u64 t, %1; cvt.u32.u64 %0, t; }"
        : "=r"(a) : "l"(p));
    return a;
}

__device__ __forceinline__ void cp_async16(uint32_t dst, const void* src) {
    asm volatile("cp.async.cg.shared.global [%0], [%1], 16;"
                 :: "r"(dst), "l"(src) : "memory");
}
#define CP_COMMIT() asm volatile("cp.async.commit_group;" ::: "memory")
#define CP_WAIT(n)  asm volatile("cp.async.wait_group %0;" :: "n"(n) : "memory")

// D = A(16x8) * B(8x8) + D, tf32 inputs, fp32 accum.
__device__ __forceinline__ void mma_tf32(float* c, const uint32_t* a, const uint32_t* b) {
    asm volatile(
        "mma.sync.aligned.m16n8k8.row.col.f32.tf32.tf32.f32 "
        "{%0,%1,%2,%3}, {%4,%5,%6,%7}, {%8,%9}, {%0,%1,%2,%3};"
        : "+f"(c[0]), "+f"(c[1]), "+f"(c[2]), "+f"(c[3])
        : "r"(a[0]), "r"(a[1]), "r"(a[2]), "r"(a[3]),
          "r"(b[0]), "r"(b[1]));
}

// ---------------------------------------------------------------------------
// Elementwise tf32 rounding: out[i] = round_rna_tf32(in[i])
// ---------------------------------------------------------------------------
__global__ void round_tf32_kernel(const float* __restrict__ in,
                                  float* __restrict__ out, int n4)
{
    int i = blockIdx.x * blockDim.x + threadIdx.x;
    if (i < n4) {
        float4 v = *(const float4*)&in[(size_t)i * 4];
        uint4 u = make_uint4(f2tf32(v.x), f2tf32(v.y), f2tf32(v.z), f2tf32(v.w));
        *(uint4*)&out[(size_t)i * 4] = u;
    }
}

// ---------------------------------------------------------------------------
// tf32 tensor-core GEMM: C[M,N] = A[M,K] @ B[K,N] + bias[N]
// 128x128x32 tile, 256 threads (8 warps 2x4, warp tile 64x32).
// A,B pre-rounded to tf32. cp.async double-buffered.
// ---------------------------------------------------------------------------
constexpr int G_LDA = 36;    // A tile stride (words): banks (4r+c)%32 conflict-free
constexpr int G_LDB = 136;   // B tile stride (words): banks (8t+g)%32 conflict-free
constexpr int G_STAGE = 128 * G_LDA + 32 * G_LDB;  // 8960 words
constexpr int GEMM_SMEM = 2 * G_STAGE * 4;         // 71680 B

__device__ __forceinline__ void gemm_load_stage(
    const float* __restrict__ A, const float* __restrict__ Bm,
    int K, int N, int bm, int bn, int slab,
    uint32_t s_a, uint32_t s_b, int tid)
{
    const float* Ag = A + (size_t)bm * K + slab * 32;
    #pragma unroll
    for (int l = 0; l < 4; ++l) {
        int id = tid + l * 256;
        int r = id >> 3, c = (id & 7) * 4;          // 128 rows x 8 chunks
        cp_async16(s_a + (uint32_t)(r * G_LDA + c) * 4, Ag + (size_t)r * K + c);
    }
    const float* Bg = Bm + (size_t)(slab * 32) * N + bn;
    #pragma unroll
    for (int l = 0; l < 4; ++l) {
        int id = tid + l * 256;
        int r = id >> 5, c = (id & 31) * 4;         // 32 rows x 32 chunks
        cp_async16(s_b + (uint32_t)(r * G_LDB + c) * 4, Bg + (size_t)r * N + c);
    }
    CP_COMMIT();
}

__global__ __launch_bounds__(256, 2) void gemm_mma_kernel(
    const float* __restrict__ A, const float* __restrict__ Bm,
    const float* __restrict__ bias, float* __restrict__ Cm,
    int M, int N, int K, int round_out)
{
    extern __shared__ __align__(16) uint32_t gsm[];
    const uint32_t sb = smem_to_u32(gsm);

    const int tid  = threadIdx.x;
    const int w    = tid >> 5;
    const int lane = tid & 31;
    const int g    = lane >> 2;
    const int t    = lane & 3;
    const int wm   = w >> 2;
    const int wn   = w & 3;
    const int bm   = blockIdx.y * 128;
    const int bn   = blockIdx.x * 128;

    float acc[4][4][4];
    #pragma unroll
    for (int mi = 0; mi < 4; ++mi)
        #pragma unroll
        for (int ni = 0; ni < 4; ++ni)
            #pragma unroll
            for (int c = 0; c < 4; ++c) acc[mi][ni][c] = 0.f;

    const int nslab = K / 32;
    gemm_load_stage(A, Bm, K, N, bm, bn, 0, sb, sb + 128 * G_LDA * 4, tid);

    for (int i = 0; i < nslab; ++i) {
        const int buf = i & 1;
        if (i + 1 < nslab) {
            uint32_t so = sb + (uint32_t)((buf ^ 1) * G_STAGE) * 4;
            gemm_load_stage(A, Bm, K, N, bm, bn, i + 1, so, so + 128 * G_LDA * 4, tid);
            CP_WAIT(1);
        } else {
            CP_WAIT(0);
        }
        __syncthreads();

        const uint32_t* As = gsm + buf * G_STAGE;
        const uint32_t* Bs = As + 128 * G_LDA;

        #pragma unroll
        for (int kc = 0; kc < 4; ++kc) {
            uint32_t af[4][4], bf[4][2];
            #pragma unroll
            for (int mi = 0; mi < 4; ++mi) {
                int rb = wm * 64 + mi * 16;
                af[mi][0] = As[(rb + g    ) * G_LDA + kc * 8 + t    ];
                af[mi][1] = As[(rb + g + 8) * G_LDA + kc * 8 + t    ];
                af[mi][2] = As[(rb + g    ) * G_LDA + kc * 8 + t + 4];
                af[mi][3] = As[(rb + g + 8) * G_LDA + kc * 8 + t + 4];
            }
            #pragma unroll
            for (int ni = 0; ni < 4; ++ni) {
                int nb = wn * 32 + ni * 8;
                bf[ni][0] = Bs[(kc * 8 + t    ) * G_LDB + nb + g];
                bf[ni][1] = Bs[(kc * 8 + t + 4) * G_LDB + nb + g];
            }
            #pragma unroll
            for (int mi = 0; mi < 4; ++mi)
                #pragma unroll
                for (int ni = 0; ni < 4; ++ni)
                    mma_tf32(acc[mi][ni], af[mi], bf[ni]);
        }
        __syncthreads();
    }

    // Epilogue: bias, optional tf32 rounding of outputs, store
    #pragma unroll
    for (int mi = 0; mi < 4; ++mi) {
        int r0 = bm + wm * 64 + mi * 16 + g;
        #pragma unroll
        for (int ni = 0; ni < 4; ++ni) {
            int col = bn + wn * 32 + ni * 8 + 2 * t;
            float b0 = bias[col], b1 = bias[col + 1];
            float v00 = acc[mi][ni][0] + b0, v01 = acc[mi][ni][1] + b1;
            float v10 = acc[mi][ni][2] + b0, v11 = acc[mi][ni][3] + b1;
            if (round_out) {
                v00 = __uint_as_float(f2tf32(v00));
                v01 = __uint_as_float(f2tf32(v01));
                v10 = __uint_as_float(f2tf32(v10));
                v11 = __uint_as_float(f2tf32(v11));
            }
            *(float2*)&Cm[(size_t)r0 * N + col]       = make_float2(v00, v01);
            *(float2*)&Cm[(size_t)(r0 + 8) * N + col] = make_float2(v10, v11);
        }
    }
}

// ---------------------------------------------------------------------------
// Flash attention (causal), tf32 mma.sync, cp.async double-buffered K/V.
// Grid (T/128, H, B), block 256 (8 warps; warp owns 16 q-rows). K tile 64.
// qkv is pre-rounded tf32 (GEMM1 epilogue). y stored tf32-rounded.
// ---------------------------------------------------------------------------
constexpr int A_LDK = 68;   // K tile stride (words)
constexpr int A_LDV = 72;   // V tile stride (words)
constexpr int A_LDP = 68;   // P / Q staging stride (words)
// word offsets
constexpr int OFF_K0 = 0;
constexpr int OFF_K1 = 64 * A_LDK;                 // 4352
constexpr int OFF_V0 = 2 * 64 * A_LDK;             // 8704
constexpr int OFF_V1 = OFF_V0 + 64 * A_LDV;        // 13312
constexpr int OFF_P  = OFF_V0 + 2 * 64 * A_LDV;    // 17920
constexpr int ATTN_SMEM = (OFF_P + 128 * A_LDP) * 4;  // 106496 B

__device__ __forceinline__ void attn_load_kv(
    const float* __restrict__ qkv, int b, int h, int ktile,
    uint32_t s_k, uint32_t s_v, int tid)
{
    const float* Kg = qkv + ((size_t)(b * Tc + ktile * 64)) * Wqkv + Cc + h * DH;
    const float* Vg = Kg + Cc;
    #pragma unroll
    for (int l = 0; l < 4; ++l) {
        int id = tid + l * 256;
        int r = id >> 4, c = (id & 15) * 4;   // 64 rows x 16 chunks
        cp_async16(s_k + (uint32_t)(r * A_LDK + c) * 4, Kg + (size_t)r * Wqkv + c);
    }
    #pragma unroll
    for (int l = 0; l < 4; ++l) {
        int id = tid + l * 256;
        int r = id >> 4, c = (id & 15) * 4;
        cp_async16(s_v + (uint32_t)(r * A_LDV + c) * 4, Vg + (size_t)r * Wqkv + c);
    }
    CP_COMMIT();
}

__global__ __launch_bounds__(256) void attn_tc_kernel(
    const float* __restrict__ qkv, float* __restrict__ y)
{
    extern __shared__ __align__(16) uint32_t asm_[];
    const uint32_t sb = smem_to_u32(asm_);
    uint32_t* Ps = asm_ + OFF_P;

    const int tid  = threadIdx.x;
    const int w    = tid >> 5;
    const int lane = tid & 31;
    const int g    = lane >> 2;
    const int t    = lane & 3;
    const int rb   = w * 16;            // warp's q-row base (0..112)

    const int qt = blockIdx.x;          // 128-row q tile
    const int h  = blockIdx.y;
    const int b  = blockIdx.z;

    // Stage Q tile [128][64] into Ps via cp.async (group 1)
    {
        const float* Qg = qkv + ((size_t)(b * Tc + qt * 128)) * Wqkv + h * DH;
        #pragma unroll
        for (int l = 0; l < 8; ++l) {
            int id = tid + l * 256;
            int r = id >> 4, c = (id & 15) * 4;   // 128 rows x 16 chunks
            cp_async16(sb + (uint32_t)(OFF_P + r * A_LDP + c) * 4,
                       Qg + (size_t)r * Wqkv + c);
        }
        CP_COMMIT();
    }
    // Prefetch K/V tile 0 (group 2)
    attn_load_kv(qkv, b, h, 0, sb + OFF_K0 * 4, sb + OFF_V0 * 4, tid);

    // Wait for Q (allow KV0 to stay in flight), extract Q fragments, scale
    CP_WAIT(1);
    __syncthreads();
    uint32_t qa[8][4];
    #pragma unroll
    for (int kc = 0; kc < 8; ++kc) {
        uint32_t r0 = Ps[(rb + g    ) * A_LDP + kc * 8 + t    ];
        uint32_t r1 = Ps[(rb + g + 8) * A_LDP + kc * 8 + t    ];
        uint32_t r2 = Ps[(rb + g    ) * A_LDP + kc * 8 + t + 4];
        uint32_t r3 = Ps[(rb + g + 8) * A_LDP + kc * 8 + t + 4];
        // exact scale by 1/8 (power of two; stays on tf32 grid)
        qa[kc][0] = __float_as_uint(__uint_as_float(r0) * 0.125f);
        qa[kc][1] = __float_as_uint(__uint_as_float(r1) * 0.125f);
        qa[kc][2] = __float_as_uint(__uint_as_float(r2) * 0.125f);
        qa[kc][3] = __float_as_uint(__uint_as_float(r3) * 0.125f);
    }

    float o[8][4];
    #pragma unroll
    for (int nf = 0; nf < 8; ++nf)
        #pragma unroll
        for (int c = 0; c < 4; ++c) o[nf][c] = 0.f;
    float m0 = -1e30f, m1 = -1e30f, l0 = 0.f, l1 = 0.f;

    const int nk = 2 * qt + 2;                 // 64-wide k tiles
    const int qr0g = qt * 128 + rb + g;        // global q rows for this thread
    const int qr1g = qr0g + 8;

    for (int kt = 0; kt < nk; ++kt) {
        const int buf = kt & 1;
        if (kt + 1 < nk) {
            attn_load_kv(qkv, b, h, kt + 1,
                         sb + (buf ? OFF_K0 : OFF_K1) * 4,
                         sb + (buf ? OFF_V0 : OFF_V1) * 4, tid);
            CP_WAIT(1);
        } else {
            CP_WAIT(0);
        }
        __syncthreads();

        const uint32_t* Ks = asm_ + (buf ? OFF_K1 : OFF_K0);
        const uint32_t* Vs = asm_ + (buf ? OFF_V1 : OFF_V0);

        // S = Q K^T
        float s[8][4];
        #pragma unroll
        for (int ni = 0; ni < 8; ++ni)
            #pragma unroll
            for (int c = 0; c < 4; ++c) s[ni][c] = 0.f;

        #pragma unroll
        for (int kc = 0; kc < 8; ++kc) {
            #pragma unroll
            for (int ni = 0; ni < 8; ++ni) {
                uint32_t bf[2];
                bf[0] = Ks[(ni * 8 + g) * A_LDK + kc * 8 + t    ];
                bf[1] = Ks[(ni * 8 + g) * A_LDK + kc * 8 + t + 4];
                mma_tf32(s[ni], qa[kc], bf);
            }
        }

        // Causal mask (only tiles overlapping the diagonal)
        if (kt >= 2 * qt) {
            int colb = kt * 64;
            #pragma unroll
            for (int ni = 0; ni < 8; ++ni) {
                int c0 = colb + ni * 8 + 2 * t, c1 = c0 + 1;
                if (c0 > qr0g) s[ni][0] = -1e30f;
                if (c1 > qr0g) s[ni][1] = -1e30f;
                if (c0 > qr1g) s[ni][2] = -1e30f;
                if (c1 > qr1g) s[ni][3] = -1e30f;
            }
        }

        // Online softmax (rows g and g+8; stats over the quad)
        float mx0 = -1e30f, mx1 = -1e30f;
        #pragma unroll
        for (int ni = 0; ni < 8; ++ni) {
            mx0 = fmaxf(mx0, fmaxf(s[ni][0], s[ni][1]));
            mx1 = fmaxf(mx1, fmaxf(s[ni][2], s[ni][3]));
        }
        mx0 = fmaxf(mx0, __shfl_xor_sync(0xffffffffu, mx0, 1));
        mx0 = fmaxf(mx0, __shfl_xor_sync(0xffffffffu, mx0, 2));
        mx1 = fmaxf(mx1, __shfl_xor_sync(0xffffffffu, mx1, 1));
        mx1 = fmaxf(mx1, __shfl_xor_sync(0xffffffffu, mx1, 2));

        float mn0 = fmaxf(m0, mx0), mn1 = fmaxf(m1, mx1);
        float a0 = __expf(m0 - mn0), a1 = __expf(m1 - mn1);

        float rs0 = 0.f, rs1 = 0.f;
        #pragma unroll
        for (int ni = 0; ni < 8; ++ni) {
            s[ni][0] = __expf(s[ni][0] - mn0);
            s[ni][1] = __expf(s[ni][1] - mn0);
            s[ni][2] = __expf(s[ni][2] - mn1);
            s[ni][3] = __expf(s[ni][3] - mn1);
            rs0 += s[ni][0] + s[ni][1];
            rs1 += s[ni][2] + s[ni][3];
        }
        rs0 += __shfl_xor_sync(0xffffffffu, rs0, 1);
        rs0 += __shfl_xor_sync(0xffffffffu, rs0, 2);
        rs1 += __shfl_xor_sync(0xffffffffu, rs1, 1);
        rs1 += __shfl_xor_sync(0xffffffffu, rs1, 2);

        l0 = l0 * a0 + rs0;  m0 = mn0;
        l1 = l1 * a1 + rs1;  m1 = mn1;

        #pragma unroll
        for (int nf = 0; nf < 8; ++nf) {
            o[nf][0] *= a0; o[nf][1] *= a0;
            o[nf][2] *= a1; o[nf][3] *= a1;
        }

        // Stage P (warp-private rows)
        #pragma unroll
        for (int ni = 0; ni < 8; ++ni) {
            int c0 = ni * 8 + 2 * t;
            Ps[(rb + g    ) * A_LDP + c0    ] = f2tf32(s[ni][0]);
            Ps[(rb + g    ) * A_LDP + c0 + 1] = f2tf32(s[ni][1]);
            Ps[(rb + g + 8) * A_LDP + c0    ] = f2tf32(s[ni][2]);
            Ps[(rb + g + 8) * A_LDP + c0 + 1] = f2tf32(s[ni][3]);
        }
        __syncwarp();

        // O += P @ V
        #pragma unroll
        for (int kc = 0; kc < 8; ++kc) {
            uint32_t pa[4];
            pa[0] = Ps[(rb + g    ) * A_LDP + kc * 8 + t    ];
            pa[1] = Ps[(rb + g + 8) * A_LDP + kc * 8 + t    ];
            pa[2] = Ps[(rb + g    ) * A_LDP + kc * 8 + t + 4];
            pa[3] = Ps[(rb + g + 8) * A_LDP + kc * 8 + t + 4];
            #pragma unroll
            for (int nf = 0; nf < 8; ++nf) {
                uint32_t bf[2];
                bf[0] = Vs[(kc * 8 + t    ) * A_LDV + nf * 8 + g];
                bf[1] = Vs[(kc * 8 + t + 4) * A_LDV + nf * 8 + g];
                mma_tf32(o[nf], pa, bf);
            }
        }
        __syncthreads();
    }

    // Epilogue: normalize, round to tf32 (GEMM2 would round anyway), store
    float inv0 = 1.f / l0, inv1 = 1.f / l1;
    float* Yg = y + ((size_t)(b * Tc + qt * 128)) * Cc + h * DH;
    #pragma unroll
    for (int nf = 0; nf < 8; ++nf) {
        int c0 = nf * 8 + 2 * t;
        float2 v0 = make_float2(__uint_as_float(f2tf32(o[nf][0] * inv0)),
                                __uint_as_float(f2tf32(o[nf][1] * inv0)));
        float2 v1 = make_float2(__uint_as_float(f2tf32(o[nf][2] * inv1)),
                                __uint_as_float(f2tf32(o[nf][3] * inv1)));
        *(float2*)&Yg[(size_t)(rb + g    ) * Cc + c0] = v0;
        *(float2*)&Yg[(size_t)(rb + g + 8) * Cc + c0] = v1;
    }
}

// ---------------------------------------------------------------------------
// Launch
// ---------------------------------------------------------------------------
extern "C" void kernel_launch(void* const* d_in, const int* in_sizes, int n_in,
                              void* d_out, int out_size)
{
    const float* x      = (const float*)d_in[0];
    const float* W_attn = (const float*)d_in[1];
    const float* b_attn = (const float*)d_in[2];
    const float* W_proj = (const float*)d_in[3];
    const float* b_proj = (const float*)d_in[4];
    float* out = (float*)d_out;

    float *qkv_p, *y_p, *xr_p, *w1r_p, *w2r_p;
    cudaGetSymbolAddress((void**)&qkv_p, g_qkv);
    cudaGetSymbolAddress((void**)&y_p,   g_y);
    cudaGetSymbolAddress((void**)&xr_p,  g_xr);
    cudaGetSymbolAddress((void**)&w1r_p, g_w1r);
    cudaGetSymbolAddress((void**)&w2r_p, g_w2r);

    cudaFuncSetAttribute(gemm_mma_kernel,
                         cudaFuncAttributeMaxDynamicSharedMemorySize, GEMM_SMEM);
    cudaFuncSetAttribute(attn_tc_kernel,
                         cudaFuncAttributeMaxDynamicSharedMemorySize, ATTN_SMEM);

    // 0) Pre-round operands to tf32 (rna)
    {
        int n4;
        n4 = (Mrows * Cc) / 4;
        round_tf32_kernel<<<(n4 + 255) / 256, 256>>>(x, xr_p, n4);
        n4 = (Cc * Wqkv) / 4;
        round_tf32_kernel<<<(n4 + 255) / 256, 256>>>(W_attn, w1r_p, n4);
        n4 = (Cc * Cc) / 4;
        round_tf32_kernel<<<(n4 + 255) / 256, 256>>>(W_proj, w2r_p, n4);
    }

    // 1) QKV = x @ W_attn + b_attn   [4096, 3072], outputs tf32-rounded
    gemm_mma_kernel<<<dim3(Wqkv / 128, Mrows / 128), 256, GEMM_SMEM>>>(
        xr_p, w1r_p, b_attn, qkv_p, Mrows, Wqkv, Cc, 1);

    // 2) causal flash attention -> g_y (tf32-rounded)
    attn_tc_kernel<<<dim3(Tc / 128, HEAD, Bc), 256, ATTN_SMEM>>>(qkv_p, y_p);

    // 3) out = y @ W_proj + b_proj   [4096, 1024], full fp32 out
    gemm_mma_kernel<<<dim3(Cc / 128, Mrows / 128), 256, GEMM_SMEM>>>(
        y_p, w2r_p, b_proj, out, Mrows, Cc, Cc, 0);
}

// round 7
// speedup vs baseline: 3.4374x; 1.0501x over previous
#include <cuda_runtime.h>
#include <cuda_bf16.h>
#include <cstdint>

// Problem constants
constexpr int Bc    = 2;
constexpr int Tc    = 2048;
constexpr int Cc    = 1024;
constexpr int HEAD  = 16;
constexpr int DH    = 64;
constexpr int Wqkv  = 3 * Cc;     // 3072
constexpr int Mrows = Bc * Tc;    // 4096

// Scratch (allocation-free rule: device globals)
__device__ float g_qkv[(size_t)Mrows * Wqkv]; // [B,T,3C], tf32-rounded
__device__ float g_y  [(size_t)Mrows * Cc];   // [B,T,C],  tf32-rounded
__device__ float g_xr [(size_t)Mrows * Cc];   // x tf32-rounded [M][K]
__device__ float g_w1t[(size_t)Wqkv * Cc];    // W_attn^T [N][K], tf32-rounded
__device__ float g_w2t[(size_t)Cc * Cc];      // W_proj^T [N][K], tf32-rounded

// ---------------------------------------------------------------------------
// Helpers
// ---------------------------------------------------------------------------
__device__ __forceinline__ uint32_t f2tf32(float x) {
    uint32_t r;
    asm("cvt.rna.tf32.f32 %0, %1;" : "=r"(r) : "f"(x));
    return r;
}

__device__ __forceinline__ uint32_t smem_to_u32(const void* p) {
    uint32_t a;
    asm("{ .reg .u64 t; cvta.to.shared.u64 t, %1; cvt.u32.u64 %0, t; }"
        : "=r"(a) : "l"(p));
    return a;
}

__device__ __forceinline__ void cp_async16(uint32_t dst, const void* src) {
    asm volatile("cp.async.cg.shared.global [%0], [%1], 16;"
                 :: "r"(dst), "l"(src) : "memory");
}
#define CP_COMMIT() asm volatile("cp.async.commit_group;" ::: "memory")
#define CP_WAIT(n)  asm volatile("cp.async.wait_group %0;" :: "n"(n) : "memory")

// ldmatrix x4: four 8x8 b16 tiles == four 8x4 b32 tiles.
// Lane L supplies the row address for matrix L/8, row L%8 (16B rows).
// Result: for matrix m, reg d[m] of lane L = tile_m[row L/4][b32col L%4].
__device__ __forceinline__ void ldsm_x4(uint32_t addr, uint32_t* d) {
    asm volatile("ldmatrix.sync.aligned.m8n8.x4.shared.b16 {%0,%1,%2,%3}, [%4];"
                 : "=r"(d[0]), "=r"(d[1]), "=r"(d[2]), "=r"(d[3]) : "r"(addr));
}

// D = A(16x8) * B(8x8) + D, tf32 inputs, fp32 accum.
__device__ __forceinline__ void mma_tf32(float* c, const uint32_t* a, const uint32_t* b) {
    asm volatile(
        "mma.sync.aligned.m16n8k8.row.col.f32.tf32.tf32.f32 "
        "{%0,%1,%2,%3}, {%4,%5,%6,%7}, {%8,%9}, {%0,%1,%2,%3};"
        : "+f"(c[0]), "+f"(c[1]), "+f"(c[2]), "+f"(c[3])
        : "r"(a[0]), "r"(a[1]), "r"(a[2]), "r"(a[3]),
          "r"(b[0]), "r"(b[1]));
}

// ---------------------------------------------------------------------------
// Elementwise tf32 rounding
// ---------------------------------------------------------------------------
__global__ void round_tf32_kernel(const float* __restrict__ in,
                                  float* __restrict__ out, int n4)
{
    int i = blockIdx.x * blockDim.x + threadIdx.x;
    if (i < n4) {
        float4 v = *(const float4*)&in[(size_t)i * 4];
        uint4 u = make_uint4(f2tf32(v.x), f2tf32(v.y), f2tf32(v.z), f2tf32(v.w));
        *(uint4*)&out[(size_t)i * 4] = u;
    }
}

// Transpose + tf32-round: in[K][N] -> out[N][K]
__global__ void transpose_tf32_kernel(const float* __restrict__ in,
                                      float* __restrict__ out, int K, int N)
{
    __shared__ float tile[32][33];
    int k0 = blockIdx.y * 32, n0 = blockIdx.x * 32;
    int tx = threadIdx.x, ty = threadIdx.y;  // 32 x 8
    #pragma unroll
    for (int i = 0; i < 32; i += 8)
        tile[ty + i][tx] = in[(size_t)(k0 + ty + i) * N + n0 + tx];
    __syncthreads();
    #pragma unroll
    for (int i = 0; i < 32; i += 8)
        out[(size_t)(n0 + ty + i) * K + k0 + tx] =
            __uint_as_float(f2tf32(tile[tx][ty + i]));
}

// ---------------------------------------------------------------------------
// tf32 GEMM: C[M,N] = A[M,K] @ Bt[N,K]^T + bias[N]
// 128x128x32 tile, 256 threads (8 warps 2x4, warp tile 64x32).
// A [M][K], Bt [N][K], both pre-rounded tf32. 3-stage cp.async + ldmatrix.
// ---------------------------------------------------------------------------
constexpr int G_LD    = 36;                 // tile row stride (words), both A & B
constexpr int G_STAGE = 2 * 128 * G_LD;     // words per stage (A tile + B tile)
constexpr int G_NSTG  = 3;
constexpr int GEMM_SMEM = G_NSTG * G_STAGE * 4;  // 110592 B

__device__ __forceinline__ void gemm_load_stage(
    const float* __restrict__ A, const float* __restrict__ Bt,
    int K, int bm, int bn, int slab, uint32_t s_stage, int tid)
{
    const float* Ag = A + (size_t)bm * K + slab * 32;
    #pragma unroll
    for (int l = 0; l < 4; ++l) {
        int id = tid + l * 256;
        int r = id >> 3, c = (id & 7) * 4;          // 128 rows x 8 chunks
        cp_async16(s_stage + (uint32_t)(r * G_LD + c) * 4, Ag + (size_t)r * K + c);
    }
    const float* Bg = Bt + (size_t)bn * K + slab * 32;
    uint32_t s_b = s_stage + 128 * G_LD * 4;
    #pragma unroll
    for (int l = 0; l < 4; ++l) {
        int id = tid + l * 256;
        int r = id >> 3, c = (id & 7) * 4;          // 128 n-rows x 8 chunks
        cp_async16(s_b + (uint32_t)(r * G_LD + c) * 4, Bg + (size_t)r * K + c);
    }
    CP_COMMIT();
}

__global__ __launch_bounds__(256, 2) void gemm_mma_kernel(
    const float* __restrict__ A, const float* __restrict__ Bt,
    const float* __restrict__ bias, float* __restrict__ Cm,
    int M, int N, int K, int round_out)
{
    extern __shared__ __align__(16) uint32_t gsm[];
    const uint32_t sb = smem_to_u32(gsm);

    const int tid  = threadIdx.x;
    const int w    = tid >> 5;
    const int lane = tid & 31;
    const int g    = lane >> 2;
    const int t    = lane & 3;
    const int wm   = w >> 2;
    const int wn   = w & 3;
    const int bm   = blockIdx.y * 128;
    const int bn   = blockIdx.x * 128;

    // ldmatrix per-lane address components
    const int lrow = lane & 7, lmat = lane >> 3;
    // A frags: matrix m -> rows rb + (m&1)*8, cols (m>>1)*4 (+ kc*8)
    const uint32_t a_frag_off =
        (uint32_t)(((wm * 64 + (lmat & 1) * 8 + lrow) * G_LD + (lmat >> 1) * 4) * 4);
    // B frags: matrix m -> n rows nb + (m>>1)*8, k cols (m&1)*4 (+ kc*8)
    const uint32_t b_frag_off =
        (uint32_t)(((wn * 32 + (lmat >> 1) * 8 + lrow) * G_LD + (lmat & 1) * 4) * 4);

    float acc[4][4][4];
    #pragma unroll
    for (int mi = 0; mi < 4; ++mi)
        #pragma unroll
        for (int ni = 0; ni < 4; ++ni)
            #pragma unroll
            for (int c = 0; c < 4; ++c) acc[mi][ni][c] = 0.f;

    const int nslab = K / 32;
    gemm_load_stage(A, Bt, K, bm, bn, 0, sb, tid);
    if (nslab > 1) gemm_load_stage(A, Bt, K, bm, bn, 1, sb + G_STAGE * 4, tid);

    int stg = 0;
    for (int i = 0; i < nslab; ++i) {
        if (i + 2 < nslab) {
            int s2 = (stg + 2) % G_NSTG;
            gemm_load_stage(A, Bt, K, bm, bn, i + 2, sb + (uint32_t)s2 * G_STAGE * 4, tid);
            CP_WAIT(2);
        } else if (i + 1 < nslab) {
            CP_WAIT(1);
        } else {
            CP_WAIT(0);
        }
        __syncthreads();

        const uint32_t a_base = sb + (uint32_t)stg * G_STAGE * 4 + a_frag_off;
        const uint32_t b_base = sb + (uint32_t)stg * G_STAGE * 4 + 128 * G_LD * 4 + b_frag_off;

        #pragma unroll
        for (int kc = 0; kc < 4; ++kc) {
            const uint32_t ko = (uint32_t)kc * 32;   // 8 b32 cols = 32 B
            uint32_t af[4][4], bf[2][4];
            #pragma unroll
            for (int mi = 0; mi < 4; ++mi)
                ldsm_x4(a_base + (uint32_t)mi * (16 * G_LD * 4) + ko, af[mi]);
            #pragma unroll
            for (int p = 0; p < 2; ++p)
                ldsm_x4(b_base + (uint32_t)p * (16 * G_LD * 4) + ko, bf[p]);
            #pragma unroll
            for (int mi = 0; mi < 4; ++mi) {
                mma_tf32(acc[mi][0], af[mi], &bf[0][0]);
                mma_tf32(acc[mi][1], af[mi], &bf[0][2]);
                mma_tf32(acc[mi][2], af[mi], &bf[1][0]);
                mma_tf32(acc[mi][3], af[mi], &bf[1][2]);
            }
        }
        __syncthreads();
        stg = (stg + 1) % G_NSTG;
    }

    // Epilogue
    #pragma unroll
    for (int mi = 0; mi < 4; ++mi) {
        int r0 = bm + wm * 64 + mi * 16 + g;
        #pragma unroll
        for (int ni = 0; ni < 4; ++ni) {
            int col = bn + wn * 32 + ni * 8 + 2 * t;
            float b0 = bias[col], b1 = bias[col + 1];
            float v00 = acc[mi][ni][0] + b0, v01 = acc[mi][ni][1] + b1;
            float v10 = acc[mi][ni][2] + b0, v11 = acc[mi][ni][3] + b1;
            if (round_out) {
                v00 = __uint_as_float(f2tf32(v00));
                v01 = __uint_as_float(f2tf32(v01));
                v10 = __uint_as_float(f2tf32(v10));
                v11 = __uint_as_float(f2tf32(v11));
            }
            *(float2*)&Cm[(size_t)r0 * N + col]       = make_float2(v00, v01);
            *(float2*)&Cm[(size_t)(r0 + 8) * N + col] = make_float2(v10, v11);
        }
    }
}

// ---------------------------------------------------------------------------
// Flash attention (causal), tf32 mma.sync + ldmatrix, cp.async K/V.
// Grid (T/128, H, B), block 256 (8 warps; warp owns 16 q-rows). K tile 64.
// ---------------------------------------------------------------------------
constexpr int A_LDK = 68;
constexpr int A_LDV = 72;
constexpr int A_LDP = 68;
constexpr int OFF_K0 = 0;
constexpr int OFF_K1 = 64 * A_LDK;
constexpr int OFF_V0 = 2 * 64 * A_LDK;
constexpr int OFF_V1 = OFF_V0 + 64 * A_LDV;
constexpr int OFF_P  = OFF_V0 + 2 * 64 * A_LDV;
constexpr int ATTN_SMEM = (OFF_P + 128 * A_LDP) * 4;   // 106496 B

__device__ __forceinline__ void attn_load_kv(
    const float* __restrict__ qkv, int b, int h, int ktile,
    uint32_t s_k, uint32_t s_v, int tid)
{
    const float* Kg = qkv + ((size_t)(b * Tc + ktile * 64)) * Wqkv + Cc + h * DH;
    const float* Vg = Kg + Cc;
    #pragma unroll
    for (int l = 0; l < 4; ++l) {
        int id = tid + l * 256;
        int r = id >> 4, c = (id & 15) * 4;
        cp_async16(s_k + (uint32_t)(r * A_LDK + c) * 4, Kg + (size_t)r * Wqkv + c);
    }
    #pragma unroll
    for (int l = 0; l < 4; ++l) {
        int id = tid + l * 256;
        int r = id >> 4, c = (id & 15) * 4;
        cp_async16(s_v + (uint32_t)(r * A_LDV + c) * 4, Vg + (size_t)r * Wqkv + c);
    }
    CP_COMMIT();
}

__global__ __launch_bounds__(256) void attn_tc_kernel(
    const float* __restrict__ qkv, float* __restrict__ y)
{
    extern __shared__ __align__(16) uint32_t asm_[];
    const uint32_t sb = smem_to_u32(asm_);
    uint32_t* Ps = asm_ + OFF_P;

    const int tid  = threadIdx.x;
    const int w    = tid >> 5;
    const int lane = tid & 31;
    const int g    = lane >> 2;
    const int t    = lane & 3;
    const int rb   = w * 16;

    // heavy tiles first (causal imbalance)
    const int qt = (int)gridDim.x - 1 - (int)blockIdx.x;
    const int h  = blockIdx.y;
    const int b  = blockIdx.z;

    const int lrow = lane & 7, lmat = lane >> 3;
    // A-layout frag offset into Ps (used for both Q and P fragments)
    const uint32_t p_frag_off =
        (uint32_t)(((rb + (lmat & 1) * 8 + lrow) * A_LDP + (lmat >> 1) * 4) * 4);
    // B-layout frag offset into K tiles (token-major)
    const uint32_t k_frag_off =
        (uint32_t)((((lmat >> 1) * 8 + lrow) * A_LDK + (lmat & 1) * 4) * 4);

    // Stage Q tile [128][64] into Ps (group 1)
    {
        const float* Qg = qkv + ((size_t)(b * Tc + qt * 128)) * Wqkv + h * DH;
        #pragma unroll
        for (int l = 0; l < 8; ++l) {
            int id = tid + l * 256;
            int r = id >> 4, c = (id & 15) * 4;
            cp_async16(sb + (uint32_t)(OFF_P + r * A_LDP + c) * 4,
                       Qg + (size_t)r * Wqkv + c);
        }
        CP_COMMIT();
    }
    attn_load_kv(qkv, b, h, 0, sb + OFF_K0 * 4, sb + OFF_V0 * 4, tid);

    CP_WAIT(1);
    __syncthreads();

    // Q fragments via ldmatrix, scaled by 1/8 (exact power of two)
    uint32_t qa[8][4];
    #pragma unroll
    for (int kc = 0; kc < 8; ++kc) {
        ldsm_x4(sb + OFF_P * 4 + p_frag_off + (uint32_t)kc * 32, qa[kc]);
        #pragma unroll
        for (int j = 0; j < 4; ++j)
            qa[kc][j] = __float_as_uint(__uint_as_float(qa[kc][j]) * 0.125f);
    }

    float o[8][4];
    #pragma unroll
    for (int nf = 0; nf < 8; ++nf)
        #pragma unroll
        for (int c = 0; c < 4; ++c) o[nf][c] = 0.f;
    float m0 = -1e30f, m1 = -1e30f, l0 = 0.f, l1 = 0.f;

    const int nk   = 2 * qt + 2;
    const int qr0g = qt * 128 + rb + g;
    const int qr1g = qr0g + 8;

    for (int kt = 0; kt < nk; ++kt) {
        const int buf = kt & 1;
        if (kt + 1 < nk) {
            attn_load_kv(qkv, b, h, kt + 1,
                         sb + (buf ? OFF_K0 : OFF_K1) * 4,
                         sb + (buf ? OFF_V0 : OFF_V1) * 4, tid);
            CP_WAIT(1);
        } else {
            CP_WAIT(0);
        }
        __syncthreads();

        const uint32_t k_base = sb + (buf ? OFF_K1 : OFF_K0) * 4 + k_frag_off;
        const uint32_t* Vs = asm_ + (buf ? OFF_V1 : OFF_V0);

        // S = Q K^T via ldmatrix B-frags (Ks is token-major = n-major)
        float s[8][4];
        #pragma unroll
        for (int ni = 0; ni < 8; ++ni)
            #pragma unroll
            for (int c = 0; c < 4; ++c) s[ni][c] = 0.f;

        #pragma unroll
        for (int kc = 0; kc < 8; ++kc) {
            const uint32_t ko = (uint32_t)kc * 32;
            #pragma unroll
            for (int p = 0; p < 4; ++p) {
                uint32_t kb[4];
                ldsm_x4(k_base + (uint32_t)p * (16 * A_LDK * 4) + ko, kb);
                mma_tf32(s[2 * p    ], qa[kc], &kb[0]);
                mma_tf32(s[2 * p + 1], qa[kc], &kb[2]);
            }
        }

        // Causal mask (only tiles overlapping the diagonal)
        if (kt >= 2 * qt) {
            int colb = kt * 64;
            #pragma unroll
            for (int ni = 0; ni < 8; ++ni) {
                int c0 = colb + ni * 8 + 2 * t, c1 = c0 + 1;
                if (c0 > qr0g) s[ni][0] = -1e30f;
                if (c1 > qr0g) s[ni][1] = -1e30f;
                if (c0 > qr1g) s[ni][2] = -1e30f;
                if (c1 > qr1g) s[ni][3] = -1e30f;
            }
        }

        // Online softmax
        float mx0 = -1e30f, mx1 = -1e30f;
        #pragma unroll
        for (int ni = 0; ni < 8; ++ni) {
            mx0 = fmaxf(mx0, fmaxf(s[ni][0], s[ni][1]));
            mx1 = fmaxf(mx1, fmaxf(s[ni][2], s[ni][3]));
        }
        mx0 = fmaxf(mx0, __shfl_xor_sync(0xffffffffu, mx0, 1));
        mx0 = fmaxf(mx0, __shfl_xor_sync(0xffffffffu, mx0, 2));
        mx1 = fmaxf(mx1, __shfl_xor_sync(0xffffffffu, mx1, 1));
        mx1 = fmaxf(mx1, __shfl_xor_sync(0xffffffffu, mx1, 2));

        float mn0 = fmaxf(m0, mx0), mn1 = fmaxf(m1, mx1);
        float a0 = __expf(m0 - mn0), a1 = __expf(m1 - mn1);

        float rs0 = 0.f, rs1 = 0.f;
        #pragma unroll
        for (int ni = 0; ni < 8; ++ni) {
            s[ni][0] = __expf(s[ni][0] - mn0);
            s[ni][1] = __expf(s[ni][1] - mn0);
            s[ni][2] = __expf(s[ni][2] - mn1);
            s[ni][3] = __expf(s[ni][3] - mn1);
            rs0 += s[ni][0] + s[ni][1];
            rs1 += s[ni][2] + s[ni][3];
        }
        rs0 += __shfl_xor_sync(0xffffffffu, rs0, 1);
        rs0 += __shfl_xor_sync(0xffffffffu, rs0, 2);
        rs1 += __shfl_xor_sync(0xffffffffu, rs1, 1);
        rs1 += __shfl_xor_sync(0xffffffffu, rs1, 2);

        l0 = l0 * a0 + rs0;  m0 = mn0;
        l1 = l1 * a1 + rs1;  m1 = mn1;

        #pragma unroll
        for (int nf = 0; nf < 8; ++nf) {
            o[nf][0] *= a0; o[nf][1] *= a0;
            o[nf][2] *= a1; o[nf][3] *= a1;
        }

        // Stage P (warp-private rows), 64-bit stores
        #pragma unroll
        for (int ni = 0; ni < 8; ++ni) {
            int c0 = ni * 8 + 2 * t;
            uint2 v0 = make_uint2(f2tf32(s[ni][0]), f2tf32(s[ni][1]));
            uint2 v1 = make_uint2(f2tf32(s[ni][2]), f2tf32(s[ni][3]));
            *(uint2*)&Ps[(rb + g    ) * A_LDP + c0] = v0;
            *(uint2*)&Ps[(rb + g + 8) * A_LDP + c0] = v1;
        }
        __syncwarp();

        // O += P @ V  (pa via ldmatrix; V frags scalar, conflict-free)
        #pragma unroll
        for (int kc = 0; kc < 8; ++kc) {
            uint32_t pa[4];
            ldsm_x4(sb + OFF_P * 4 + p_frag_off + (uint32_t)kc * 32, pa);
            #pragma unroll
            for (int nf = 0; nf < 8; ++nf) {
                uint32_t bf[2];
                bf[0] = Vs[(kc * 8 + t    ) * A_LDV + nf * 8 + g];
                bf[1] = Vs[(kc * 8 + t + 4) * A_LDV + nf * 8 + g];
                mma_tf32(o[nf], pa, bf);
            }
        }
        __syncwarp();
        __syncthreads();
    }

    // Epilogue: normalize, round to tf32, store
    float inv0 = 1.f / l0, inv1 = 1.f / l1;
    float* Yg = y + ((size_t)(b * Tc + qt * 128)) * Cc + h * DH;
    #pragma unroll
    for (int nf = 0; nf < 8; ++nf) {
        int c0 = nf * 8 + 2 * t;
        float2 v0 = make_float2(__uint_as_float(f2tf32(o[nf][0] * inv0)),
                                __uint_as_float(f2tf32(o[nf][1] * inv0)));
        float2 v1 = make_float2(__uint_as_float(f2tf32(o[nf][2] * inv1)),
                                __uint_as_float(f2tf32(o[nf][3] * inv1)));
        *(float2*)&Yg[(size_t)(rb + g    ) * Cc + c0] = v0;
        *(float2*)&Yg[(size_t)(rb + g + 8) * Cc + c0] = v1;
    }
}

// ---------------------------------------------------------------------------
// Launch
// ---------------------------------------------------------------------------
extern "C" void kernel_launch(void* const* d_in, const int* in_sizes, int n_in,
                              void* d_out, int out_size)
{
    const float* x      = (const float*)d_in[0];
    const float* W_attn = (const float*)d_in[1];
    const float* b_attn = (const float*)d_in[2];
    const float* W_proj = (const float*)d_in[3];
    const float* b_proj = (const float*)d_in[4];
    float* out = (float*)d_out;

    float *qkv_p, *y_p, *xr_p, *w1t_p, *w2t_p;
    cudaGetSymbolAddress((void**)&qkv_p, g_qkv);
    cudaGetSymbolAddress((void**)&y_p,   g_y);
    cudaGetSymbolAddress((void**)&xr_p,  g_xr);
    cudaGetSymbolAddress((void**)&w1t_p, g_w1t);
    cudaGetSymbolAddress((void**)&w2t_p, g_w2t);

    cudaFuncSetAttribute(gemm_mma_kernel,
                         cudaFuncAttributeMaxDynamicSharedMemorySize, GEMM_SMEM);
    cudaFuncSetAttribute(attn_tc_kernel,
                         cudaFuncAttributeMaxDynamicSharedMemorySize, ATTN_SMEM);

    // 0) Pre-round x; transpose+round weights to [N][K]
    {
        int n4 = (Mrows * Cc) / 4;
        round_tf32_kernel<<<(n4 + 255) / 256, 256>>>(x, xr_p, n4);
        transpose_tf32_kernel<<<dim3(Wqkv / 32, Cc / 32), dim3(32, 8)>>>(W_attn, w1t_p, Cc, Wqkv);
        transpose_tf32_kernel<<<dim3(Cc / 32,  Cc / 32), dim3(32, 8)>>>(W_proj, w2t_p, Cc, Cc);
    }

    // 1) QKV = x @ W_attn + b_attn   [4096, 3072], outputs tf32-rounded
    gemm_mma_kernel<<<dim3(Wqkv / 128, Mrows / 128), 256, GEMM_SMEM>>>(
        xr_p, w1t_p, b_attn, qkv_p, Mrows, Wqkv, Cc, 1);

    // 2) causal flash attention -> g_y (tf32-rounded)
    attn_tc_kernel<<<dim3(Tc / 128, HEAD, Bc), 256, ATTN_SMEM>>>(qkv_p, y_p);

    // 3) out = y @ W_proj + b_proj   [4096, 1024], full fp32 out
    gemm_mma_kernel<<<dim3(Cc / 128, Mrows / 128), 256, GEMM_SMEM>>>(
        y_p, w2t_p, b_proj, out, Mrows, Cc, Cc, 0);
}